// round 17
// baseline (speedup 1.0000x reference)
#include <cuda_runtime.h>
#include <cuda_bf16.h>
#include <cstdint>

// Problem constants
#define B_      32
#define C_      512
#define HW_     4096            // 64*64
#define NPIX    (B_ * HW_)      // 131072
#define M_      1024
#define THRESH  0.8f
#define MSCALE  16.0f           // fp8 scale applied to normalized memory rows
#define NTILES  (NPIX / 64)     // 2048
#define GRID_P  444             // 148 SMs * 3 CTAs

// ---------------------------------------------------------------------------
// Device scratch (no cudaMalloc allowed)
// ---------------------------------------------------------------------------
__device__ uint8_t g_mem8[M_ * C_];                 // normalized memory * 16, e4m3
__device__ uint8_t g_x8[(size_t)NPIX * C_];         // x transposed [pix][k], e4m3
__device__ float   g_pnorm2[NPIX];                  // exact fp32 ||x||^2
__device__ int     g_tile_ctr;                      // persistent-kernel counter

__device__ __forceinline__ uint32_t smem_u32(const void* p) {
    uint32_t a;
    asm("{ .reg .u64 t; cvta.to.shared.u64 t, %1; cvt.u32.u64 %0, t; }" : "=r"(a) : "l"(p));
    return a;
}

__device__ __forceinline__ void ldsm_x4(uint32_t* r, uint32_t addr) {
    asm volatile("ldmatrix.sync.aligned.m8n8.x4.shared.b16 {%0,%1,%2,%3}, [%4];"
        : "=r"(r[0]), "=r"(r[1]), "=r"(r[2]), "=r"(r[3]) : "r"(addr));
}

__device__ __forceinline__ void mma_fp8(float* d, const uint32_t* a, const uint32_t* b) {
    asm volatile("mma.sync.aligned.m16n8k32.row.col.f32.e4m3.e4m3.f32 "
        "{%0,%1,%2,%3}, {%4,%5,%6,%7}, {%8,%9}, {%0,%1,%2,%3};"
        : "+f"(d[0]), "+f"(d[1]), "+f"(d[2]), "+f"(d[3])
        : "r"(a[0]), "r"(a[1]), "r"(a[2]), "r"(a[3]), "r"(b[0]), "r"(b[1]));
}

// pack 2 floats -> 2 e4m3 bytes (same helper for x and memory: consistent
// k-permutation, dot-invariant). lo -> low byte, hi -> high byte.
__device__ __forceinline__ uint16_t pk2(float lo, float hi) {
    uint16_t r;
    asm("cvt.rn.satfinite.e4m3x2.f32 %0, %1, %2;" : "=h"(r) : "f"(hi), "f"(lo));
    return r;
}

__device__ __forceinline__ void cp16(uint32_t dst, const void* src) {
    asm volatile("cp.async.cg.shared.global [%0], [%1], 16;" :: "r"(dst), "l"(src));
}
#define CP_COMMIT() asm volatile("cp.async.commit_group;" ::: "memory")
#define CP_WAIT0()  asm volatile("cp.async.wait_group 0;" ::: "memory")

// ---------------------------------------------------------------------------
// Kernel 0: normalize memory rows -> e4m3 (scaled by 16); resets tile counter.
// ---------------------------------------------------------------------------
__global__ void norm_mem_kernel(const float* __restrict__ mem) {
    int row = blockIdx.x;
    int t   = threadIdx.x;   // 128 threads, 4 floats each
    if (row == 0 && t == 0) g_tile_ctr = 0;
    const float4* r = (const float4*)(mem + (size_t)row * C_);
    float4 v = r[t];
    float ss = v.x * v.x + v.y * v.y + v.z * v.z + v.w * v.w;
#pragma unroll
    for (int o = 16; o; o >>= 1) ss += __shfl_xor_sync(0xffffffffu, ss, o);
    __shared__ float ws[4];
    if ((t & 31) == 0) ws[t >> 5] = ss;
    __syncthreads();
    float tot = ws[0] + ws[1] + ws[2] + ws[3];
    float inv = MSCALE / fmaxf(sqrtf(tot), 1e-12f);
    uint16_t a = pk2(v.x * inv, v.y * inv);
    uint16_t b = pk2(v.z * inv, v.w * inv);
    ((uint32_t*)(g_mem8 + (size_t)row * C_))[t] = (uint32_t)a | ((uint32_t)b << 16);
}

// ---------------------------------------------------------------------------
// Kernel 1: transpose + e4m3-convert + exact norm, bandwidth-bound.
// Block = 64 pixels x all 512 channels, 256 threads. The fp32->fp8 cvt cost
// hides under DRAM latency here instead of blocking the MMA kernel.
// ---------------------------------------------------------------------------
__global__ __launch_bounds__(256) void xpose_norm8_kernel(const float* __restrict__ x) {
    __shared__ float xs[64][65];
    int bid = blockIdx.x;
    int ht = bid & 63;            // hw tile
    int b  = bid >> 6;            // batch
    int t  = threadIdx.x;
    int hw = t & 63;
    int cl = t >> 6;              // 0..3
    int px = t >> 2;              // 0..63
    int ch = (t & 3) * 16;        // 16-channel slice
    float ss = 0.f;
    const float* xb = x + (size_t)b * C_ * HW_ + ht * 64;

    for (int ct = 0; ct < 8; ct++) {
        const float* src = xb + (size_t)(ct * 64) * HW_;
#pragma unroll
        for (int i = 0; i < 16; i++) {
            xs[cl + i * 4][hw] = src[(size_t)(cl + i * 4) * HW_ + hw];
        }
        __syncthreads();
        uint16_t h8[8];
#pragma unroll
        for (int j = 0; j < 8; j++) {
            float a  = xs[ch + 2 * j][px];
            float c2 = xs[ch + 2 * j + 1][px];
            ss += a * a + c2 * c2;
            h8[j] = pk2(a, c2);
        }
        uint4 r4;
        r4.x = (uint32_t)h8[0] | ((uint32_t)h8[1] << 16);
        r4.y = (uint32_t)h8[2] | ((uint32_t)h8[3] << 16);
        r4.z = (uint32_t)h8[4] | ((uint32_t)h8[5] << 16);
        r4.w = (uint32_t)h8[6] | ((uint32_t)h8[7] << 16);
        size_t p = (size_t)b * HW_ + ht * 64 + px;
        *(uint4*)(g_x8 + p * C_ + ct * 64 + ch) = r4;
        __syncthreads();
    }
    ss += __shfl_xor_sync(0xffffffffu, ss, 1);
    ss += __shfl_xor_sync(0xffffffffu, ss, 2);
    if ((t & 3) == 0) g_pnorm2[(size_t)b * HW_ + ht * 64 + px] = ss;
}

// ---------------------------------------------------------------------------
// Kernel 2: PERSISTENT fp8 GEMM+argmax, 3 CTAs/SM, 444 CTAs.
// Prologue is now a single 34KB cp.async batch (pre-converted A); the
// deferred output write of tile T-1 hides under it.
// ---------------------------------------------------------------------------
#define A_PITCH    528
#define B_PITCH    144
#define OFF_B      33792         // 64 * 528
#define B_CHUNK    18432         // 128 * 144
#define OFF_REDV   70656         // OFF_B + 2*B_CHUNK
#define OFF_REDI   71680
#define OFF_SEL    72704         // 64 ints
#define OFF_TILE   72960
#define SMEM_BYTES 73088

__global__ __launch_bounds__(256, 3) void sim_fused_kernel(
    const float* __restrict__ memf,
    float* __restrict__ out
) {
    extern __shared__ char smem[];
    uint32_t sb = smem_u32(smem);
    float* redv = (float*)(smem + OFF_REDV);   // [64][4]
    int*   redi = (int*)(smem + OFF_REDI);     // [64][4]
    int*   ssel = (int*)(smem + OFF_SEL);      // [64]
    int*   tsh  = (int*)(smem + OFF_TILE);

    int t    = threadIdx.x;
    int lane = t & 31;
    int w    = t >> 5;
    int wr   = w & 1;      // pixel half (32 px)
    int wc   = w >> 1;     // m quarter (32 m)

    // ---- tile-invariant ldmatrix addresses ----
    uint32_t aAddr[2];
#pragma unroll
    for (int i = 0; i < 2; i++)
        aAddr[i] = sb + (uint32_t)(wr * 32 + i * 16 + (lane & 15)) * A_PITCH
                      + (uint32_t)(lane >> 4) * 16u;
    uint32_t bAddr[2];
#pragma unroll
    for (int jp = 0; jp < 2; jp++)
        bAddr[jp] = sb + OFF_B
                  + (uint32_t)(wc * 32 + (2 * jp + (lane >> 4)) * 8 + (lane & 7)) * B_PITCH
                  + (uint32_t)((lane >> 3) & 1) * 16u;

    // ---- hoisted per-thread cp.async offsets ----
    uint32_t bSm[4];  size_t bGm[4];
#pragma unroll
    for (int i = 0; i < 4; i++) {
        int idx = t + i * 256;                 // B: m = idx>>3, q = idx&7
        bSm[i] = sb + OFF_B + (uint32_t)((idx >> 3) * B_PITCH + (idx & 7) * 16);
        bGm[i] = (size_t)(idx >> 3) * C_ + (size_t)(idx & 7) * 16;
    }
    uint32_t aSm[8];  size_t aGm[8];
#pragma unroll
    for (int i = 0; i < 8; i++) {
        int idx = t + i * 256;                 // A: px = idx>>5, q = idx&31
        aSm[i] = sb + (uint32_t)((idx >> 5) * A_PITCH + (idx & 31) * 16);
        aGm[i] = (size_t)(idx >> 5) * C_ + (size_t)(idx & 31) * 16;
    }

    auto loadB = [&](int nt, int kc, int buf) {
        const char* bsrc = (const char*)g_mem8 + (size_t)(nt * 128) * C_ + kc * 128;
        uint32_t bo = (uint32_t)buf * B_CHUNK;
#pragma unroll
        for (int i = 0; i < 4; i++) cp16(bSm[i] + bo, bsrc + bGm[i]);
        CP_COMMIT();
    };

    int pb = -1, phw0 = 0;     // deferred-output tile coords

    // ================= PERSISTENT TILE LOOP ================================
    for (;;) {
        if (t == 0) *tsh = atomicAdd(&g_tile_ctr, 1);
        __syncthreads();
        int tile = *tsh;
        if (tile >= NTILES) break;

        int pix0 = tile * 64;
        int b    = pix0 >> 12;
        int hw0  = pix0 & (HW_ - 1);

        // ---- async: B chunk 0 + entire A tile (pre-converted fp8) ----
        loadB(0, 0, 0);
        {
            const char* asrc = (const char*)g_x8 + (size_t)pix0 * C_;
#pragma unroll
            for (int i = 0; i < 8; i++) cp16(aSm[i], asrc + aGm[i]);
            CP_COMMIT();
        }

        // per-pixel norm for this tile (used only by t<64 in the epilogue;
        // issued early so latency hides under the mainloop)
        float pnv = (t < 64) ? g_pnorm2[pix0 + t] : 0.f;

        // ---- DEFERRED OUTPUT for previous tile (hides under cp.async) ----
        if (pb >= 0) {
            int q4 = (t & 15) * 4;           // pixel quad
            int c0 = t >> 4;                 // 0..15
            int s0 = ssel[q4 + 0];
            int s1 = ssel[q4 + 1];
            int s2 = ssel[q4 + 2];
            int s3 = ssel[q4 + 3];
            const float* mr0 = memf + (size_t)(s0 < 0 ? 0 : s0) * C_;
            const float* mr1 = memf + (size_t)(s1 < 0 ? 0 : s1) * C_;
            const float* mr2 = memf + (size_t)(s2 < 0 ? 0 : s2) * C_;
            const float* mr3 = memf + (size_t)(s3 < 0 ? 0 : s3) * C_;
            float* ob = out + ((size_t)pb * C_) * HW_ + phw0 + q4;
#pragma unroll 8
            for (int i = 0; i < 32; i++) {
                int c = c0 + i * 16;
                float4 v;
                v.x = (s0 >= 0) ? mr0[c] : 0.f;
                v.y = (s1 >= 0) ? mr1[c] : 0.f;
                v.z = (s2 >= 0) ? mr2[c] : 0.f;
                v.w = (s3 >= 0) ? mr3[c] : 0.f;
                *(float4*)(ob + (size_t)c * HW_) = v;
            }
        }

        // ============ MAINLOOP: fp8 QMMA GEMM + argmax ======================
        float bestv[2][2];
        int   besti[2][2];
#pragma unroll
        for (int i = 0; i < 2; i++) {
            bestv[i][0] = -1e30f; bestv[i][1] = -1e30f;
            besti[i][0] = 0;      besti[i][1] = 0;
        }

        for (int nt = 0; nt < 8; nt++) {
            float acc[2][4][4];
#pragma unroll
            for (int i = 0; i < 2; i++)
#pragma unroll
                for (int j = 0; j < 4; j++)
#pragma unroll
                    for (int r = 0; r < 4; r++) acc[i][j][r] = 0.f;

            for (int kc = 0; kc < 4; kc++) {          // 4 chunks of k=128
                CP_WAIT0();        // chunk kc (and A on first iter) arrived
                __syncthreads();   // visible everywhere; compute(kc-1) done
                {
                    int nkc = kc + 1, nnt = nt;
                    if (nkc == 4) { nkc = 0; nnt = nt + 1; }
                    if (nnt < 8) loadB(nnt, nkc, (kc + 1) & 1);
                }
                uint32_t bufOff = (uint32_t)((kc & 1) * B_CHUNK);
                uint32_t kcOff  = (uint32_t)(kc * 128);   // 128 fp8 bytes/chunk
#pragma unroll
                for (int ks = 0; ks < 4; ks++) {
                    uint32_t ko = (uint32_t)(ks * 32);    // one k32 step
                    uint32_t af[2][4];
#pragma unroll
                    for (int i = 0; i < 2; i++)
                        ldsm_x4(af[i], aAddr[i] + kcOff + ko);
                    uint32_t bfr[2][4];
#pragma unroll
                    for (int jp = 0; jp < 2; jp++)
                        ldsm_x4(bfr[jp], bAddr[jp] + bufOff + ko);
#pragma unroll
                    for (int i = 0; i < 2; i++)
#pragma unroll
                        for (int j = 0; j < 4; j++)
                            mma_fp8(acc[i][j], af[i], &bfr[j >> 1][(j & 1) * 2]);
                }
            }

            // fold N-tile into running argmax (first-max tie-break)
#pragma unroll
            for (int i = 0; i < 2; i++)
#pragma unroll
                for (int rp = 0; rp < 2; rp++)
#pragma unroll
                    for (int j = 0; j < 4; j++)
#pragma unroll
                        for (int c = 0; c < 2; c++) {
                            float v = acc[i][j][rp * 2 + c];
                            if (v > bestv[i][rp]) {
                                bestv[i][rp] = v;
                                besti[i][rp] = nt * 128 + wc * 32 + j * 8 + (lane & 3) * 2 + c;
                            }
                        }
        }

        // ============ EPILOGUE: reductions + selection ======================
#pragma unroll
        for (int i = 0; i < 2; i++)
#pragma unroll
            for (int rp = 0; rp < 2; rp++) {
                float v = bestv[i][rp];
                int   ix = besti[i][rp];
#pragma unroll
                for (int off = 1; off <= 2; off <<= 1) {
                    float ov = __shfl_xor_sync(0xffffffffu, v, off);
                    int   oi = __shfl_xor_sync(0xffffffffu, ix, off);
                    if (ov > v || (ov == v && oi < ix)) { v = ov; ix = oi; }
                }
                if ((lane & 3) == 0) {
                    int row = wr * 32 + i * 16 + (lane >> 2) + rp * 8;
                    redv[row * 4 + wc] = v;
                    redi[row * 4 + wc] = ix;
                }
            }
        __syncthreads();
        if (t < 64) {
            float bv = redv[t * 4];
            int   bi = redi[t * 4];
#pragma unroll
            for (int j = 1; j < 4; j++) {
                float v = redv[t * 4 + j];
                if (v > bv) { bv = v; bi = redi[t * 4 + j]; }
            }
            // dot_q ~ 16 * (x . m_hat); fire iff dot_q > 0.8 * 16 * ||x||
            ssel[t] = (bv > (THRESH * MSCALE) * sqrtf(pnv)) ? bi : -1;
        }
        __syncthreads();

        pb = b; phw0 = hw0;    // defer output into next tile's async window
    }

    // ---- flush last tile's output ----
    if (pb >= 0) {
        int q4 = (t & 15) * 4;
        int c0 = t >> 4;
        int s0 = ssel[q4 + 0];
        int s1 = ssel[q4 + 1];
        int s2 = ssel[q4 + 2];
        int s3 = ssel[q4 + 3];
        const float* mr0 = memf + (size_t)(s0 < 0 ? 0 : s0) * C_;
        const float* mr1 = memf + (size_t)(s1 < 0 ? 0 : s1) * C_;
        const float* mr2 = memf + (size_t)(s2 < 0 ? 0 : s2) * C_;
        const float* mr3 = memf + (size_t)(s3 < 0 ? 0 : s3) * C_;
        float* ob = out + ((size_t)pb * C_) * HW_ + phw0 + q4;
#pragma unroll 8
        for (int i = 0; i < 32; i++) {
            int c = c0 + i * 16;
            float4 v;
            v.x = (s0 >= 0) ? mr0[c] : 0.f;
            v.y = (s1 >= 0) ? mr1[c] : 0.f;
            v.z = (s2 >= 0) ? mr2[c] : 0.f;
            v.w = (s3 >= 0) ? mr3[c] : 0.f;
            *(float4*)(ob + (size_t)c * HW_) = v;
        }
    }
}

// ---------------------------------------------------------------------------
extern "C" void kernel_launch(void* const* d_in, const int* in_sizes, int n_in,
                              void* d_out, int out_size) {
    const float* x   = (const float*)d_in[0];   // 32*512*64*64
    const float* mem = (const float*)d_in[1];   // 1024*512
    float* out = (float*)d_out;

    cudaFuncSetAttribute(sim_fused_kernel,
                         cudaFuncAttributeMaxDynamicSharedMemorySize, SMEM_BYTES);

    norm_mem_kernel<<<M_, 128>>>(mem);
    xpose_norm8_kernel<<<B_ * 64, 256>>>(x);
    sim_fused_kernel<<<GRID_P, 256, SMEM_BYTES>>>(mem, out);
}